// round 2
// baseline (speedup 1.0000x reference)
#include <cuda_runtime.h>
#include <math.h>

// Problem constants (fixed shapes: features [16,512,768] f32, labels [16,512] i32)
#define H      768
#define NCLS   10
#define TPB    256
#define NBLK   256         // accumulation blocks
#define RPB    32          // rows per block  (N = NBLK*RPB = 8192)
#define RPI    8           // rows per iteration (in-flight)
#define ITERS  (RPB / RPI)
#define TEMPERATURE 0.07
#define EPS    1e-12f

// Device scratch (no allocations allowed). Fully overwritten every launch.
__device__ float g_part[NBLK * NCLS * H];   // per-block class sums (~7.9 MB)
__device__ int   g_cnt [NBLK * NCLS];       // per-block class counts
__device__ float g_cs  [NCLS * H];          // reduced class sums

// ---------------------------------------------------------------------------
// Kernel 1: normalize rows, accumulate per-class sums into smem, flush.
// ---------------------------------------------------------------------------
__global__ __launch_bounds__(TPB) void supcon_accum(
    const float* __restrict__ feat,
    const int* __restrict__ labels)          // int32 (JAX downcasts int64)
{
    __shared__ float acc[NCLS * H];      // 30720 B
    __shared__ float red[RPI * 8];       // per-warp partial sums, 8 warps
    __shared__ float inv[RPI];
    __shared__ int   labs[RPI];
    __shared__ int   cnts[NCLS];

    const int tid  = threadIdx.x;
    const int lane = tid & 31;
    const int warp = tid >> 5;

    for (int i = tid; i < NCLS * H; i += TPB) acc[i] = 0.0f;
    if (tid < NCLS) cnts[tid] = 0;
    __syncthreads();

    const int row0 = blockIdx.x * RPB;

    for (int it = 0; it < ITERS; ++it) {
        const int base = row0 + it * RPI;

        // Load RPI rows: 24 independent global loads per thread (high MLP).
        float v[RPI][3];
        float ss[RPI];
        #pragma unroll
        for (int j = 0; j < RPI; ++j) {
            const float* x = feat + (size_t)(base + j) * H;
            v[j][0] = x[tid];
            v[j][1] = x[tid + 256];
            v[j][2] = x[tid + 512];
        }

        // labels for this group (clamped: a bad label must never OOB smem)
        if (tid < RPI) {
            int l = labels[base + tid];
            labs[tid] = min(max(l, 0), NCLS - 1);
        }

        #pragma unroll
        for (int j = 0; j < RPI; ++j)
            ss[j] = v[j][0]*v[j][0] + v[j][1]*v[j][1] + v[j][2]*v[j][2];

        // Warp-level reduce all RPI sums
        #pragma unroll
        for (int o = 16; o > 0; o >>= 1) {
            #pragma unroll
            for (int j = 0; j < RPI; ++j)
                ss[j] += __shfl_xor_sync(0xffffffffu, ss[j], o);
        }
        if (lane == 0) {
            #pragma unroll
            for (int j = 0; j < RPI; ++j)
                red[j * 8 + warp] = ss[j];
        }
        __syncthreads();   // sync1

        // Cross-warp reduce: 64 lanes, groups of 8 (j = tid>>3, w = tid&7)
        if (tid < RPI * 8) {
            float s = red[tid];
            s += __shfl_xor_sync(0xffffffffu, s, 4);
            s += __shfl_xor_sync(0xffffffffu, s, 2);
            s += __shfl_xor_sync(0xffffffffu, s, 1);
            if ((tid & 7) == 0)
                inv[tid >> 3] = 1.0f / fmaxf(sqrtf(s), EPS);
        }
        __syncthreads();   // sync2

        // Accumulate normalized rows into class accumulators.
        // Each thread owns h = {tid, tid+256, tid+512} -> no smem races.
        #pragma unroll
        for (int j = 0; j < RPI; ++j) {
            const float iv = inv[j];
            float* a = acc + labs[j] * H;
            a[tid]       += v[j][0] * iv;
            a[tid + 256] += v[j][1] * iv;
            a[tid + 512] += v[j][2] * iv;
        }
        if (tid < RPI) atomicAdd(&cnts[labs[tid]], 1);
        __syncthreads();   // sync3 (protect red/inv/labs reuse)
    }

    // Flush partials with plain stores (no global atomics, no zero-pass).
    float* dst = g_part + (size_t)blockIdx.x * (NCLS * H);
    for (int i = tid; i < NCLS * H; i += TPB) dst[i] = acc[i];
    if (tid < NCLS) g_cnt[blockIdx.x * NCLS + tid] = cnts[tid];
}

// ---------------------------------------------------------------------------
// Kernel 2: reduce per-block partials -> g_cs[c][h]
// ---------------------------------------------------------------------------
__global__ void supcon_reduce()
{
    const int i = blockIdx.x * blockDim.x + threadIdx.x;
    if (i >= NCLS * H) return;
    float s = 0.0f;
    #pragma unroll 8
    for (int b = 0; b < NBLK; ++b)
        s += g_part[(size_t)b * (NCLS * H) + i];
    g_cs[i] = s;
}

// ---------------------------------------------------------------------------
// Kernel 3: final scalar (double precision epilogue)
// ---------------------------------------------------------------------------
__global__ __launch_bounds__(TPB) void supcon_final(float* __restrict__ out,
                                                    int out_size, int N)
{
    __shared__ double sredA[8];
    __shared__ double sredP[8];
    __shared__ int    counts[NCLS];
    __shared__ float  loss_sh;

    const int tid  = threadIdx.x;
    const int lane = tid & 31;
    const int warp = tid >> 5;

    if (tid < NCLS) {
        int s = 0;
        for (int b = 0; b < NBLK; ++b) s += g_cnt[b * NCLS + tid];
        counts[tid] = s;
    }

    double p_all = 0.0, p_pos = 0.0;
    for (int h = tid; h < H; h += TPB) {
        double sh = 0.0;
        #pragma unroll
        for (int c = 0; c < NCLS; ++c) {
            double vv = (double)g_cs[c * H + h];
            sh    += vv;
            p_pos += vv * vv;
        }
        p_all += sh * sh;
    }

    // Block-reduce two doubles
    #pragma unroll
    for (int o = 16; o > 0; o >>= 1) {
        p_all += __shfl_xor_sync(0xffffffffu, p_all, o);
        p_pos += __shfl_xor_sync(0xffffffffu, p_pos, o);
    }
    if (lane == 0) { sredA[warp] = p_all; sredP[warp] = p_pos; }
    __syncthreads();

    if (tid == 0) {
        double A = 0.0, P = 0.0;
        #pragma unroll
        for (int w = 0; w < 8; ++w) { A += sredA[w]; P += sredP[w]; }

        double n_pos = 0.0;
        #pragma unroll
        for (int c = 0; c < NCLS; ++c) {
            double nc = (double)counts[c];
            n_pos += nc * nc;
        }
        double Nd    = (double)N;
        double n_neg = Nd * Nd - n_pos;

        double sum_pos = P / TEMPERATURE;
        double sum_all = A / TEMPERATURE;
        double pos_mean = sum_pos / n_pos;
        double neg_mean = (sum_all - sum_pos) / n_neg;
        double d = neg_mean - pos_mean;
        // logaddexp(0, d), numerically stable
        double loss = (d > 0.0) ? d + log1p(exp(-d)) : log1p(exp(d));
        loss_sh = (float)loss;
    }
    __syncthreads();
    for (int i = tid; i < out_size; i += TPB) out[i] = loss_sh;
}

// ---------------------------------------------------------------------------
extern "C" void kernel_launch(void* const* d_in, const int* in_sizes, int n_in,
                              void* d_out, int out_size)
{
    const float* feat   = (const float*)d_in[0];
    const int*   labels = (const int*)d_in[1];
    float*       out    = (float*)d_out;
    const int N = in_sizes[1];   // 8192

    supcon_accum <<<NBLK, TPB>>>(feat, labels);
    supcon_reduce<<<(NCLS * H + TPB - 1) / TPB, TPB>>>();
    supcon_final <<<1, TPB>>>(out, out_size, N);
}

// round 3
// speedup vs baseline: 1.1146x; 1.1146x over previous
#include <cuda_runtime.h>
#include <math.h>

// Fixed shapes: features [16,512,768] f32, labels [16,512] i32. N = 8192.
#define H      768
#define NCLS   10
#define TPB    256
#define NBLK   512         // accumulation blocks
#define RPB    16          // rows per block  (N = NBLK*RPB = 8192)
#define RPI    8           // rows per iteration (in-flight)
#define ITERS  (RPB / RPI) // 2
#define CH     (NCLS * H)  // 7680
#define RB     16          // b-slices per reduce block
#define TEMPERATURE 0.07
#define EPS    1e-12f

// Device scratch (no allocations allowed).
__device__ float g_part[NBLK * CH];   // per-block class sums (~15.7 MB)
__device__ int   g_cnt [NBLK * NCLS]; // per-block class counts
__device__ float g_cs  [CH];          // reduced class sums (zeroed inside accum)

// ---------------------------------------------------------------------------
// Kernel 1: normalize rows, accumulate per-class sums into smem, flush.
// Also zeroes g_cs (blocks 0..29), which is only consumed by the next kernel.
// ---------------------------------------------------------------------------
__global__ __launch_bounds__(TPB) void supcon_accum(
    const float* __restrict__ feat,
    const int* __restrict__ labels)
{
    __shared__ float acc[CH];            // 30720 B
    __shared__ float red[RPI * 8];       // per-warp partials, 8 warps
    __shared__ float inv[RPI];
    __shared__ int   labs[RPI];
    __shared__ int   cnts[NCLS];

    const int tid  = threadIdx.x;
    const int lane = tid & 31;
    const int warp = tid >> 5;

    // Zero g_cs for the reduce stage (strictly-before relationship via kernel order)
    if (blockIdx.x < CH / TPB)
        g_cs[blockIdx.x * TPB + tid] = 0.0f;

    for (int i = tid; i < CH; i += TPB) acc[i] = 0.0f;
    if (tid < NCLS) cnts[tid] = 0;
    __syncthreads();

    const int row0 = blockIdx.x * RPB;

    for (int it = 0; it < ITERS; ++it) {
        const int base = row0 + it * RPI;

        // 24 independent global loads per thread (high MLP).
        float v[RPI][3];
        float ss[RPI];
        #pragma unroll
        for (int j = 0; j < RPI; ++j) {
            const float* x = feat + (size_t)(base + j) * H;
            v[j][0] = x[tid];
            v[j][1] = x[tid + 256];
            v[j][2] = x[tid + 512];
        }

        if (tid < RPI) {
            int l = labels[base + tid];
            labs[tid] = min(max(l, 0), NCLS - 1);
        }

        #pragma unroll
        for (int j = 0; j < RPI; ++j)
            ss[j] = v[j][0]*v[j][0] + v[j][1]*v[j][1] + v[j][2]*v[j][2];

        #pragma unroll
        for (int o = 16; o > 0; o >>= 1) {
            #pragma unroll
            for (int j = 0; j < RPI; ++j)
                ss[j] += __shfl_xor_sync(0xffffffffu, ss[j], o);
        }
        if (lane == 0) {
            #pragma unroll
            for (int j = 0; j < RPI; ++j)
                red[j * 8 + warp] = ss[j];
        }
        __syncthreads();

        if (tid < RPI * 8) {
            float s = red[tid];
            s += __shfl_xor_sync(0xffffffffu, s, 4);
            s += __shfl_xor_sync(0xffffffffu, s, 2);
            s += __shfl_xor_sync(0xffffffffu, s, 1);
            if ((tid & 7) == 0)
                inv[tid >> 3] = 1.0f / fmaxf(sqrtf(s), EPS);
        }
        __syncthreads();

        // Each thread owns h = {tid, tid+256, tid+512} -> no smem races.
        #pragma unroll
        for (int j = 0; j < RPI; ++j) {
            const float iv = inv[j];
            float* a = acc + labs[j] * H;
            a[tid]       += v[j][0] * iv;
            a[tid + 256] += v[j][1] * iv;
            a[tid + 512] += v[j][2] * iv;
        }
        if (tid < RPI) atomicAdd(&cnts[labs[tid]], 1);
        __syncthreads();
    }

    // Flush partials with vectorized plain stores.
    float4*       dst4 = reinterpret_cast<float4*>(g_part + (size_t)blockIdx.x * CH);
    const float4* src4 = reinterpret_cast<const float4*>(acc);
    for (int i = tid; i < CH / 4; i += TPB) dst4[i] = src4[i];
    if (tid < NCLS) g_cnt[blockIdx.x * NCLS + tid] = cnts[tid];
}

// ---------------------------------------------------------------------------
// Kernel 2: parallel reduce of per-block partials -> g_cs[c][h]
// grid = (CH/TPB, NBLK/RB) = (30, 32). Each block sums RB slices, atomicAdds.
// Only 32 atomic updates per address -> negligible contention.
// ---------------------------------------------------------------------------
__global__ __launch_bounds__(TPB) void supcon_reduce()
{
    const int i  = blockIdx.x * TPB + threadIdx.x;   // 0..CH-1
    const int b0 = blockIdx.y * RB;
    float s = 0.0f;
    #pragma unroll
    for (int b = 0; b < RB; ++b)
        s += g_part[(size_t)(b0 + b) * CH + i];
    atomicAdd(&g_cs[i], s);
}

// ---------------------------------------------------------------------------
// Kernel 3: final scalar (double precision epilogue)
// ---------------------------------------------------------------------------
__global__ __launch_bounds__(TPB) void supcon_final(float* __restrict__ out,
                                                    int out_size, int N)
{
    __shared__ double sredA[8];
    __shared__ double sredP[8];
    __shared__ int    counts[NCLS];
    __shared__ float  loss_sh;

    const int tid  = threadIdx.x;
    const int lane = tid & 31;
    const int warp = tid >> 5;

    if (tid < NCLS) {
        int s = 0;
        for (int b = 0; b < NBLK; ++b) s += g_cnt[b * NCLS + tid];
        counts[tid] = s;
    }

    double p_all = 0.0, p_pos = 0.0;
    for (int h = tid; h < H; h += TPB) {
        double sh = 0.0;
        #pragma unroll
        for (int c = 0; c < NCLS; ++c) {
            double vv = (double)g_cs[c * H + h];
            sh    += vv;
            p_pos += vv * vv;
        }
        p_all += sh * sh;
    }

    #pragma unroll
    for (int o = 16; o > 0; o >>= 1) {
        p_all += __shfl_xor_sync(0xffffffffu, p_all, o);
        p_pos += __shfl_xor_sync(0xffffffffu, p_pos, o);
    }
    if (lane == 0) { sredA[warp] = p_all; sredP[warp] = p_pos; }
    __syncthreads();

    if (tid == 0) {
        double A = 0.0, P = 0.0;
        #pragma unroll
        for (int w = 0; w < 8; ++w) { A += sredA[w]; P += sredP[w]; }

        double n_pos = 0.0;
        #pragma unroll
        for (int c = 0; c < NCLS; ++c) {
            double nc = (double)counts[c];
            n_pos += nc * nc;
        }
        double Nd    = (double)N;
        double n_neg = Nd * Nd - n_pos;

        double sum_pos = P / TEMPERATURE;
        double sum_all = A / TEMPERATURE;
        double pos_mean = sum_pos / n_pos;
        double neg_mean = (sum_all - sum_pos) / n_neg;
        double d = neg_mean - pos_mean;
        double loss = (d > 0.0) ? d + log1p(exp(-d)) : log1p(exp(d));
        loss_sh = (float)loss;
    }
    __syncthreads();
    for (int i = tid; i < out_size; i += TPB) out[i] = loss_sh;
}

// ---------------------------------------------------------------------------
extern "C" void kernel_launch(void* const* d_in, const int* in_sizes, int n_in,
                              void* d_out, int out_size)
{
    const float* feat   = (const float*)d_in[0];
    const int*   labels = (const int*)d_in[1];
    float*       out    = (float*)d_out;
    const int N = in_sizes[1];   // 8192

    dim3 rgrid(CH / TPB, NBLK / RB);   // (30, 32)
    supcon_accum <<<NBLK, TPB>>>(feat, labels);
    supcon_reduce<<<rgrid, TPB>>>();
    supcon_final <<<1, TPB>>>(out, out_size, N);
}

// round 4
// speedup vs baseline: 1.1243x; 1.0087x over previous
#include <cuda_runtime.h>
#include <math.h>

// Fixed shapes: features [16,512,768] f32, labels [16,512] i32. N = 8192.
#define H      768
#define NCLS   10
#define TPB    256
#define NBLK   512          // all blocks co-resident (>=6 blocks/SM guaranteed)
#define RPB    16           // rows per block (N = NBLK*RPB = 8192)
#define RPI    8
#define ITERS  (RPB / RPI)  // 2
#define CH     (NCLS * H)   // 7680
#define RGRP   32           // partials per reduce group
#define NGRP   (NBLK / RGRP)   // 16
#define NSLICE (CH / TPB)      // 30
#define NRED   (NGRP * NSLICE) // 480 reduce blocks
#define TEMPERATURE 0.07
#define EPS    1e-12f

// Device scratch (no allocations allowed).
__device__ float    g_part[NBLK * CH];     // per-block class sums (~15.7 MB, L2-resident)
__device__ int      g_cnt [NCLS * NBLK];   // transposed counts [c][b]
__device__ float    g_cs  [CH];            // reduced class sums
__device__ int      g_cnt_tot[NCLS];
__device__ unsigned g_bar1 = 0, g_bar2 = 0; // reset by block 0 each run

__device__ __forceinline__ void block_arrive(unsigned* ctr)
{
    __threadfence();
    __syncthreads();
    if (threadIdx.x == 0) atomicAdd(ctr, 1u);
}

__device__ __forceinline__ void block_wait(unsigned* ctr)
{
    if (threadIdx.x == 0) {
        volatile unsigned* p = (volatile unsigned*)ctr;
        while (*p < NBLK) __nanosleep(128);
    }
    __syncthreads();
    __threadfence();
}

__global__ __launch_bounds__(TPB, 6) void supcon_fused(
    const float* __restrict__ feat,
    const int*   __restrict__ labels,
    float*       __restrict__ out,
    int out_size, int N)
{
    __shared__ float acc[CH];        // 30720 B
    __shared__ float redf[RPI * 8];
    __shared__ float inv[RPI];
    __shared__ int   labs[RPI];
    __shared__ int   cnts[NCLS];
    __shared__ double sredA[8];
    __shared__ double sredP[8];
    __shared__ int    iredW[8];
    __shared__ float  loss_sh;

    const int tid  = threadIdx.x;
    const int lane = tid & 31;
    const int warp = tid >> 5;
    const int bid  = blockIdx.x;

    // ---------------- Phase 1: per-block class accumulation ----------------
    if (bid < NSLICE) g_cs[bid * TPB + tid] = 0.0f;   // zero before barrier 1

    for (int i = tid; i < CH; i += TPB) acc[i] = 0.0f;
    if (tid < NCLS) cnts[tid] = 0;
    __syncthreads();

    const int row0 = bid * RPB;
    for (int it = 0; it < ITERS; ++it) {
        const int base = row0 + it * RPI;

        float v[RPI][3];
        float ss[RPI];
        #pragma unroll
        for (int j = 0; j < RPI; ++j) {
            const float* x = feat + (size_t)(base + j) * H;
            v[j][0] = x[tid];
            v[j][1] = x[tid + 256];
            v[j][2] = x[tid + 512];
        }
        if (tid < RPI) {
            int l = labels[base + tid];
            labs[tid] = min(max(l, 0), NCLS - 1);
        }
        #pragma unroll
        for (int j = 0; j < RPI; ++j)
            ss[j] = v[j][0]*v[j][0] + v[j][1]*v[j][1] + v[j][2]*v[j][2];
        #pragma unroll
        for (int o = 16; o > 0; o >>= 1) {
            #pragma unroll
            for (int j = 0; j < RPI; ++j)
                ss[j] += __shfl_xor_sync(0xffffffffu, ss[j], o);
        }
        if (lane == 0) {
            #pragma unroll
            for (int j = 0; j < RPI; ++j) redf[j * 8 + warp] = ss[j];
        }
        __syncthreads();
        if (tid < RPI * 8) {
            float s = redf[tid];
            s += __shfl_xor_sync(0xffffffffu, s, 4);
            s += __shfl_xor_sync(0xffffffffu, s, 2);
            s += __shfl_xor_sync(0xffffffffu, s, 1);
            if ((tid & 7) == 0)
                inv[tid >> 3] = 1.0f / fmaxf(sqrtf(s), EPS);
        }
        __syncthreads();
        #pragma unroll
        for (int j = 0; j < RPI; ++j) {
            const float iv = inv[j];
            float* a = acc + labs[j] * H;
            a[tid]       += v[j][0] * iv;
            a[tid + 256] += v[j][1] * iv;
            a[tid + 512] += v[j][2] * iv;
        }
        if (tid < RPI) atomicAdd(&cnts[labs[tid]], 1);
        __syncthreads();
    }

    // Flush partials (vectorized, plain stores; stays in 126MB L2)
    {
        float4*       dst4 = reinterpret_cast<float4*>(g_part + (size_t)bid * CH);
        const float4* src4 = reinterpret_cast<const float4*>(acc);
        for (int i = tid; i < CH / 4; i += TPB) dst4[i] = src4[i];
        if (tid < NCLS) g_cnt[tid * NBLK + bid] = cnts[tid];  // transposed
    }

    // ---------------- Barrier 1 ----------------
    block_arrive(&g_bar1);

    // ---------------- Phase 2: parallel reduce ----------------
    if (bid < NRED) {
        block_wait(&g_bar1);
        const int s   = bid % NSLICE;
        const int grp = bid / NSLICE;
        const int i   = s * TPB + tid;
        const int b0  = grp * RGRP;
        float sum = 0.0f;
        #pragma unroll
        for (int b = 0; b < RGRP; ++b)
            sum += g_part[(size_t)(b0 + b) * CH + i];
        atomicAdd(&g_cs[i], sum);
    } else if (bid == NRED) {
        block_wait(&g_bar1);
        // reduce counts: 10 classes x 512 blocks, coalesced
        for (int c = 0; c < NCLS; ++c) {
            int s = g_cnt[c * NBLK + tid] + g_cnt[c * NBLK + 256 + tid];
            #pragma unroll
            for (int o = 16; o > 0; o >>= 1)
                s += __shfl_xor_sync(0xffffffffu, s, o);
            if (lane == 0) iredW[warp] = s;
            __syncthreads();
            if (tid == 0) {
                int t = 0;
                #pragma unroll
                for (int w = 0; w < 8; ++w) t += iredW[w];
                g_cnt_tot[c] = t;
            }
            __syncthreads();
        }
    }
    // idle blocks (NRED+1..NBLK-1) fall through and just arrive

    // ---------------- Barrier 2 ----------------
    block_arrive(&g_bar2);
    if (bid != 0) return;

    // ---------------- Phase 3: final scalar (block 0) ----------------
    block_wait(&g_bar2);

    if (tid < NCLS) cnts[tid] = g_cnt_tot[tid];

    double p_all = 0.0, p_pos = 0.0;
    for (int h = tid; h < H; h += TPB) {
        double sh = 0.0;
        #pragma unroll
        for (int c = 0; c < NCLS; ++c) {
            double vv = (double)g_cs[c * H + h];
            sh    += vv;
            p_pos += vv * vv;
        }
        p_all += sh * sh;
    }
    #pragma unroll
    for (int o = 16; o > 0; o >>= 1) {
        p_all += __shfl_xor_sync(0xffffffffu, p_all, o);
        p_pos += __shfl_xor_sync(0xffffffffu, p_pos, o);
    }
    if (lane == 0) { sredA[warp] = p_all; sredP[warp] = p_pos; }
    __syncthreads();

    if (tid == 0) {
        double A = 0.0, P = 0.0;
        #pragma unroll
        for (int w = 0; w < 8; ++w) { A += sredA[w]; P += sredP[w]; }
        double n_pos = 0.0;
        #pragma unroll
        for (int c = 0; c < NCLS; ++c) {
            double nc = (double)cnts[c];
            n_pos += nc * nc;
        }
        double Nd    = (double)N;
        double n_neg = Nd * Nd - n_pos;
        double sum_pos = P / TEMPERATURE;
        double sum_all = A / TEMPERATURE;
        double pos_mean = sum_pos / n_pos;
        double neg_mean = (sum_all - sum_pos) / n_neg;
        double d = neg_mean - pos_mean;
        double loss = (d > 0.0) ? d + log1p(exp(-d)) : log1p(exp(d));
        loss_sh = (float)loss;
        // reset barrier counters for the next graph replay
        g_bar1 = 0;
        g_bar2 = 0;
    }
    __syncthreads();
    for (int i = tid; i < out_size; i += TPB) out[i] = loss_sh;
}

// ---------------------------------------------------------------------------
extern "C" void kernel_launch(void* const* d_in, const int* in_sizes, int n_in,
                              void* d_out, int out_size)
{
    const float* feat   = (const float*)d_in[0];
    const int*   labels = (const int*)d_in[1];
    float*       out    = (float*)d_out;
    const int N = in_sizes[1];   // 8192

    supcon_fused<<<NBLK, TPB>>>(feat, labels, out, out_size, N);
}

// round 5
// speedup vs baseline: 1.9746x; 1.7563x over previous
#include <cuda_runtime.h>
#include <math.h>

// Fixed shapes: features [16,512,768] f32, labels [16,512] i32. N = 8192.
#define H      768
#define NCLS   10
#define TPB    256
#define NBLK   512          // accumulation blocks
#define RPB    16           // rows per block (N = NBLK*RPB = 8192)
#define RPI    8
#define ITERS  (RPB / RPI)  // 2
#define CH     (NCLS * H)   // 7680
#define RGRP   32           // partials per reduce group
#define NGRP   (NBLK / RGRP)   // 16
#define NSLICE (CH / TPB)      // 30
#define NRED   (NGRP * NSLICE) // 480 reduce blocks
#define TEMPERATURE 0.07f
#define EPS    1e-12f

// Device scratch. g_cs / g_done / g_cnt_tot are zero at module load and are
// restored to zero by the last reduce block every run (self-cleaning).
__device__ float    g_part[NBLK * CH];   // per-block class sums (~15.7 MB, L2)
__device__ float    g_cs  [CH];
__device__ int      g_cnt_tot[NCLS];
__device__ unsigned g_done = 0;

// ---------------------------------------------------------------------------
// Kernel 1: normalize rows, accumulate per-class sums into smem, flush.
// ---------------------------------------------------------------------------
__global__ __launch_bounds__(TPB) void supcon_accum(
    const float* __restrict__ feat,
    const int*   __restrict__ labels)
{
    __shared__ float acc[CH];        // 30720 B
    __shared__ float redf[RPI * 8];
    __shared__ float inv[RPI];
    __shared__ int   labs[RPI];
    __shared__ int   cnts[NCLS];

    const int tid  = threadIdx.x;
    const int lane = tid & 31;
    const int warp = tid >> 5;
    const int bid  = blockIdx.x;

    for (int i = tid; i < CH; i += TPB) acc[i] = 0.0f;
    if (tid < NCLS) cnts[tid] = 0;
    __syncthreads();

    const int row0 = bid * RPB;
    for (int it = 0; it < ITERS; ++it) {
        const int base = row0 + it * RPI;

        float v[RPI][3];
        float ss[RPI];
        #pragma unroll
        for (int j = 0; j < RPI; ++j) {
            const float* x = feat + (size_t)(base + j) * H;
            v[j][0] = x[tid];
            v[j][1] = x[tid + 256];
            v[j][2] = x[tid + 512];
        }
        if (tid < RPI) {
            int l = labels[base + tid];
            labs[tid] = min(max(l, 0), NCLS - 1);
        }
        #pragma unroll
        for (int j = 0; j < RPI; ++j)
            ss[j] = v[j][0]*v[j][0] + v[j][1]*v[j][1] + v[j][2]*v[j][2];
        #pragma unroll
        for (int o = 16; o > 0; o >>= 1) {
            #pragma unroll
            for (int j = 0; j < RPI; ++j)
                ss[j] += __shfl_xor_sync(0xffffffffu, ss[j], o);
        }
        if (lane == 0) {
            #pragma unroll
            for (int j = 0; j < RPI; ++j) redf[j * 8 + warp] = ss[j];
        }
        __syncthreads();
        if (tid < RPI * 8) {
            float s = redf[tid];
            s += __shfl_xor_sync(0xffffffffu, s, 4);
            s += __shfl_xor_sync(0xffffffffu, s, 2);
            s += __shfl_xor_sync(0xffffffffu, s, 1);
            if ((tid & 7) == 0)
                inv[tid >> 3] = 1.0f / fmaxf(sqrtf(s), EPS);
        }
        __syncthreads();
        #pragma unroll
        for (int j = 0; j < RPI; ++j) {
            const float iv = inv[j];
            float* a = acc + labs[j] * H;
            a[tid]       += v[j][0] * iv;
            a[tid + 256] += v[j][1] * iv;
            a[tid + 512] += v[j][2] * iv;
        }
        if (tid < RPI) atomicAdd(&cnts[labs[tid]], 1);
        __syncthreads();
    }

    // Flush partials (vectorized plain stores) + counts (global atomics).
    float4*       dst4 = reinterpret_cast<float4*>(g_part + (size_t)bid * CH);
    const float4* src4 = reinterpret_cast<const float4*>(acc);
    for (int i = tid; i < CH / 4; i += TPB) dst4[i] = src4[i];
    if (tid < NCLS && cnts[tid] > 0) atomicAdd(&g_cnt_tot[tid], cnts[tid]);
}

// ---------------------------------------------------------------------------
// Kernel 2: reduce partials -> g_cs, last block computes the loss (all f32).
// ---------------------------------------------------------------------------
__global__ __launch_bounds__(TPB) void supcon_reduce_final(
    float* __restrict__ out, int out_size, int N)
{
    __shared__ unsigned ticket_sh;
    __shared__ float sredA[8];
    __shared__ float sredP[8];
    __shared__ float cntf[NCLS];
    __shared__ float loss_sh;

    const int tid  = threadIdx.x;
    const int lane = tid & 31;
    const int warp = tid >> 5;
    const int bid  = blockIdx.x;

    // Reduce this block's slice of partials.
    {
        const int s   = bid % NSLICE;
        const int grp = bid / NSLICE;
        const int i   = s * TPB + tid;
        const int b0  = grp * RGRP;
        float sum = 0.0f;
        #pragma unroll
        for (int b = 0; b < RGRP; ++b)
            sum += g_part[(size_t)(b0 + b) * CH + i];
        atomicAdd(&g_cs[i], sum);
    }

    // Last-block-done pattern.
    __threadfence();
    __syncthreads();
    if (tid == 0) ticket_sh = atomicAdd(&g_done, 1u);
    __syncthreads();
    if (ticket_sh != NRED - 1) return;
    __threadfence();   // acquire: make all other blocks' g_cs adds visible

    // ---- Epilogue (float) ----
    if (tid < NCLS) cntf[tid] = (float)g_cnt_tot[tid];

    float p_all = 0.0f, p_pos = 0.0f;
    #pragma unroll
    for (int k = 0; k < H / TPB; ++k) {          // 3 iterations
        const int h = k * TPB + tid;
        float sh = 0.0f;
        #pragma unroll
        for (int c = 0; c < NCLS; ++c) {
            float vv = g_cs[c * H + h];
            sh    += vv;
            p_pos += vv * vv;
        }
        p_all += sh * sh;
    }
    #pragma unroll
    for (int o = 16; o > 0; o >>= 1) {
        p_all += __shfl_xor_sync(0xffffffffu, p_all, o);
        p_pos += __shfl_xor_sync(0xffffffffu, p_pos, o);
    }
    if (lane == 0) { sredA[warp] = p_all; sredP[warp] = p_pos; }
    __syncthreads();

    if (tid == 0) {
        float A = 0.0f, P = 0.0f;
        #pragma unroll
        for (int w = 0; w < 8; ++w) { A += sredA[w]; P += sredP[w]; }
        float n_pos = 0.0f;
        #pragma unroll
        for (int c = 0; c < NCLS; ++c) n_pos += cntf[c] * cntf[c];
        float Nf    = (float)N;
        float n_neg = Nf * Nf - n_pos;

        float pos_mean = (P / TEMPERATURE) / n_pos;
        float neg_mean = ((A - P) / TEMPERATURE) / n_neg;
        float d = neg_mean - pos_mean;
        loss_sh = (d > 0.0f) ? d + log1pf(expf(-d)) : log1pf(expf(d));
    }
    __syncthreads();
    for (int i = tid; i < out_size; i += TPB) out[i] = loss_sh;

    // Restore scratch state for the next graph replay.
    for (int i = tid; i < CH; i += TPB) g_cs[i] = 0.0f;
    if (tid < NCLS) g_cnt_tot[tid] = 0;
    if (tid == 0)   g_done = 0u;
}

// ---------------------------------------------------------------------------
extern "C" void kernel_launch(void* const* d_in, const int* in_sizes, int n_in,
                              void* d_out, int out_size)
{
    const float* feat   = (const float*)d_in[0];
    const int*   labels = (const int*)d_in[1];
    float*       out    = (float*)d_out;
    const int N = in_sizes[1];   // 8192

    supcon_accum       <<<NBLK, TPB>>>(feat, labels);
    supcon_reduce_final<<<NRED, TPB>>>(out, out_size, N);
}